// round 2
// baseline (speedup 1.0000x reference)
#include <cuda_runtime.h>

// ---------------------------------------------------------------------------
// CustomGraphConv on GB300
//
//   msg[e,o]  = sum_{a,i} edge_attr[e,a] * W[a,o,i] * x[src_e, i]
//   aggr[n,o] = segment_sum over dst
//   out       = relu(aggr + bias)
//
// Factorized:
//   Phase 1: y[n,a,o] = sum_i W[a,o,i] * x[n,i]     (205M FMA, per node)
//   Phase 2: msg[e,o] = sum_a ea[e,a] * y[src,a,o]  (128 FMA/edge)
//            scatter via red.global.add.v4.f32
//   Phase 3: relu(out + bias)
//
// edge_index dtype is detected at runtime (int32 vs int64): JAX x64-disabled
// canonicalizes the reference's int64 to int32.
// ---------------------------------------------------------------------------

#define MAX_NODES 100000
#define MAX_EDGES 1600000

__device__ float g_y[MAX_NODES * 128];   // 51.2 MB (L2-resident gather target)
__device__ int   g_src[MAX_EDGES];
__device__ int   g_dst[MAX_EDGES];
__device__ int   g_is_i64;

// ---------------------------------------------------------------------------
// Detect edge_index dtype. Reads only int32 slots [0, 2*n_pairs), which is
// in-bounds for both int32 (buffer = 2E slots) and int64 (buffer = 4E slots)
// layouts. In int64 little-endian with values in [0, 100000), every odd
// int32 slot is 0; in int32 mode odd slots are random node ids.
// ---------------------------------------------------------------------------
__global__ void detect_dtype_kernel(const int* __restrict__ ei32, int n_pairs) {
    __shared__ int nonzero;
    if (threadIdx.x == 0) nonzero = 0;
    __syncthreads();
    for (int i = threadIdx.x; i < n_pairs; i += blockDim.x)
        if (ei32[2 * i + 1] != 0) nonzero = 1;   // benign race
    __syncthreads();
    if (threadIdx.x == 0) g_is_i64 = (nonzero == 0) ? 1 : 0;
}

// ---------------------------------------------------------------------------
// Convert edge_index -> compact int32 src/dst arrays (dtype-agnostic).
// ---------------------------------------------------------------------------
__global__ void convert_edges_kernel(const void* __restrict__ ei, long long E) {
    long long e = (long long)blockIdx.x * blockDim.x + threadIdx.x;
    if (e >= E) return;
    if (g_is_i64) {
        const long long* p = (const long long*)ei;
        g_src[e] = (int)p[e];
        g_dst[e] = (int)p[E + e];
    } else {
        const int* p = (const int*)ei;
        g_src[e] = p[e];
        g_dst[e] = p[E + e];
    }
}

// ---------------------------------------------------------------------------
// Phase 0: zero output (harness poisons d_out with 0xAA).
// ---------------------------------------------------------------------------
__global__ void zero_out_kernel(float4* __restrict__ out, int n4) {
    int i = blockIdx.x * blockDim.x + threadIdx.x;
    if (i < n4) out[i] = make_float4(0.f, 0.f, 0.f, 0.f);
}

// ---------------------------------------------------------------------------
// Phase 1: y[n][a][o] = dot(W[a][o][:], x[n][:]). One thread per (n, a).
// W in smem (warp-uniform broadcast reads); 64B contiguous store per thread.
// ---------------------------------------------------------------------------
__global__ void precompute_y_kernel(const float* __restrict__ x,
                                    const float* __restrict__ W,
                                    int N) {
    __shared__ float Ws[2048];  // [8][16][16]
    for (int i = threadIdx.x; i < 512; i += blockDim.x)
        ((float4*)Ws)[i] = ((const float4*)W)[i];
    __syncthreads();

    int t = blockIdx.x * blockDim.x + threadIdx.x;
    int n = t >> 3;
    int a = t & 7;
    if (n >= N) return;

    const float4* x4 = (const float4*)(x + (long long)n * 16);
    float4 xv0 = x4[0], xv1 = x4[1], xv2 = x4[2], xv3 = x4[3];

    const float4* W4 = (const float4*)(Ws + a * 256);  // [o=16][chunk=4]
    float4* y4 = (float4*)(g_y + (long long)n * 128 + a * 16);

#pragma unroll
    for (int oc = 0; oc < 4; ++oc) {
        float4 r;
        float* rp = (float*)&r;
#pragma unroll
        for (int j = 0; j < 4; ++j) {
            int o = oc * 4 + j;
            float4 w0 = W4[o * 4 + 0];
            float4 w1 = W4[o * 4 + 1];
            float4 w2 = W4[o * 4 + 2];
            float4 w3 = W4[o * 4 + 3];
            float acc = w0.x * xv0.x + w0.y * xv0.y + w0.z * xv0.z + w0.w * xv0.w;
            acc += w1.x * xv1.x + w1.y * xv1.y + w1.z * xv1.z + w1.w * xv1.w;
            acc += w2.x * xv2.x + w2.y * xv2.y + w2.z * xv2.z + w2.w * xv2.w;
            acc += w3.x * xv3.x + w3.y * xv3.y + w3.z * xv3.z + w3.w * xv3.w;
            rp[j] = acc;
        }
        y4[oc] = r;
    }
}

// ---------------------------------------------------------------------------
// Phase 2: 8 lanes per edge. y viewed as float4[32] per node; lane s loads
// chunks {s, s+8, s+16, s+24} so each 128B line is exactly one L1tex
// wavefront (4 wavefronts/edge = minimum for a 512B gather).
// chunk j = a*4 + oc: a = 2k + (s>>2), oc = s&3. shfl_xor(4) folds the
// a-halves; lanes s<4 issue one red.global.add.v4.f32 each.
// ---------------------------------------------------------------------------
__global__ void edge_scatter_kernel(const float* __restrict__ eattr,
                                    float* __restrict__ out,
                                    long long E) {
    int lane = threadIdx.x & 31;
    long long warp_global = ((long long)blockIdx.x * blockDim.x + threadIdx.x) >> 5;
    int g = lane >> 3;   // edge slot within warp
    int s = lane & 7;    // sublane within edge

    long long e = warp_global * 4 + g;
    if (e >= E) return;

    int src = g_src[e];

    const float4* y4 = (const float4*)g_y + (long long)src * 32;
    const float* ea = eattr + e * 8;
    int ab = s >> 2;
    int oc = s & 3;

    float4 acc = make_float4(0.f, 0.f, 0.f, 0.f);
#pragma unroll
    for (int k = 0; k < 4; ++k) {
        float4 v = y4[k * 8 + s];      // 8 lanes -> one 128B line
        float w = ea[2 * k + ab];      // a = 2k + ab
        acc.x += w * v.x;
        acc.y += w * v.y;
        acc.z += w * v.z;
        acc.w += w * v.w;
    }

    unsigned mask = __activemask();
    acc.x += __shfl_xor_sync(mask, acc.x, 4);
    acc.y += __shfl_xor_sync(mask, acc.y, 4);
    acc.z += __shfl_xor_sync(mask, acc.z, 4);
    acc.w += __shfl_xor_sync(mask, acc.w, 4);

    if (ab == 0) {
        int dst = g_dst[e];
        float* p = out + (long long)dst * 16 + oc * 4;
        asm volatile("red.global.add.v4.f32 [%0], {%1, %2, %3, %4};"
                     :: "l"(p), "f"(acc.x), "f"(acc.y), "f"(acc.z), "f"(acc.w)
                     : "memory");
    }
}

// ---------------------------------------------------------------------------
// Phase 3: out = relu(out + bias)
// ---------------------------------------------------------------------------
__global__ void bias_relu_kernel(float* __restrict__ out,
                                 const float* __restrict__ bias,
                                 int total4) {
    int i = blockIdx.x * blockDim.x + threadIdx.x;
    if (i >= total4) return;
    float4 v = ((float4*)out)[i];
    float4 b = ((const float4*)bias)[i & 3];
    v.x = fmaxf(v.x + b.x, 0.f);
    v.y = fmaxf(v.y + b.y, 0.f);
    v.z = fmaxf(v.z + b.z, 0.f);
    v.w = fmaxf(v.w + b.w, 0.f);
    ((float4*)out)[i] = v;
}

// ---------------------------------------------------------------------------
// inputs (metadata order): x[N,16] f32, edge_index[2,E] (i32 or i64),
//   edge_attr[E,8] f32, weight_matrix[8,16,16] f32, bias[16] f32, num_nodes
// output: [N,16] f32
// ---------------------------------------------------------------------------
extern "C" void kernel_launch(void* const* d_in, const int* in_sizes, int n_in,
                              void* d_out, int out_size) {
    const float* x = (const float*)d_in[0];
    const void* ei = d_in[1];
    const float* eattr = (const float*)d_in[2];
    const float* W = (const float*)d_in[3];
    const float* bias = (const float*)d_in[4];

    int N = in_sizes[0] / 16;
    long long E = (long long)in_sizes[2] / 8;
    float* out = (float*)d_out;

    // dtype detect + edge conversion
    {
        int n_pairs = (int)((E < 2048) ? E : 2048);
        detect_dtype_kernel<<<1, 256>>>((const int*)ei, n_pairs);
        int blocks = (int)((E + 255) / 256);
        convert_edges_kernel<<<blocks, 256>>>(ei, E);
    }
    // Phase 0: zero output
    {
        int n4 = out_size / 4;
        zero_out_kernel<<<(n4 + 255) / 256, 256>>>((float4*)out, n4);
    }
    // Phase 1: per-node precompute
    {
        int total = N * 8;
        precompute_y_kernel<<<(total + 255) / 256, 256>>>(x, W, N);
    }
    // Phase 2: edge gather/scatter
    {
        long long warps = (E + 3) / 4;
        long long threads = warps * 32;
        int blocks = (int)((threads + 255) / 256);
        edge_scatter_kernel<<<blocks, 256>>>(eattr, out, E);
    }
    // Phase 3: bias + relu
    {
        int total4 = out_size / 4;
        bias_relu_kernel<<<(total4 + 255) / 256, 256>>>(out, bias, total4);
    }
}

// round 3
// speedup vs baseline: 2.1790x; 2.1790x over previous
#include <cuda_runtime.h>

// ---------------------------------------------------------------------------
// CustomGraphConv on GB300
//
//   msg[e,o]  = sum_{a,i} edge_attr[e,a] * W[a,o,i] * x[src_e, i]
//   aggr[n,o] = segment_sum over dst
//   out       = relu(aggr + bias)
//
// Factorized:
//   Phase 1: y[n,a,o] = sum_i W[a,o,i] * x[n,i]     (205M FMA, per node)
//            -> warp-per-node-batch, W register-resident (R2 fix: the smem
//               version had an 8-way bank conflict, 180us -> L1 94.8%)
//   Phase 2: msg[e,o] = sum_a ea[e,a] * y[src,a,o]  (128 FMA/edge)
//            scatter via red.global.add.v4.f32 (L2-bound: 512B gather/edge)
//   Phase 3: relu(out + bias)
// ---------------------------------------------------------------------------

#define MAX_NODES 100000
#define MAX_EDGES 1600000
#define NODES_PER_WARP 8

__device__ float g_y[MAX_NODES * 128];   // 51.2 MB (L2-resident gather target)
__device__ int   g_src[MAX_EDGES];
__device__ int   g_dst[MAX_EDGES];
__device__ int   g_is_i64;

// ---------------------------------------------------------------------------
// Detect edge_index dtype (int32 vs int64). Reads only int32 slots
// [0, 2*n_pairs) -- in-bounds under both layouts. int64 little-endian with
// values < 100000 => every odd int32 slot is 0.
// ---------------------------------------------------------------------------
__global__ void detect_dtype_kernel(const int* __restrict__ ei32, int n_pairs) {
    __shared__ int nonzero;
    if (threadIdx.x == 0) nonzero = 0;
    __syncthreads();
    for (int i = threadIdx.x; i < n_pairs; i += blockDim.x)
        if (ei32[2 * i + 1] != 0) nonzero = 1;   // benign race
    __syncthreads();
    if (threadIdx.x == 0) g_is_i64 = (nonzero == 0) ? 1 : 0;
}

__global__ void convert_edges_kernel(const void* __restrict__ ei, long long E) {
    long long e = (long long)blockIdx.x * blockDim.x + threadIdx.x;
    if (e >= E) return;
    if (g_is_i64) {
        const long long* p = (const long long*)ei;
        g_src[e] = (int)p[e];
        g_dst[e] = (int)p[E + e];
    } else {
        const int* p = (const int*)ei;
        g_src[e] = p[e];
        g_dst[e] = p[E + e];
    }
}

// ---------------------------------------------------------------------------
// Phase 0: zero output (harness poisons d_out with 0xAA).
// ---------------------------------------------------------------------------
__global__ void zero_out_kernel(float4* __restrict__ out, int n4) {
    int i = blockIdx.x * blockDim.x + threadIdx.x;
    if (i < n4) out[i] = make_float4(0.f, 0.f, 0.f, 0.f);
}

// ---------------------------------------------------------------------------
// Phase 1: y[n][j] = sum_i W'[j][i] * x[n][i], j = a*16+o in [0,128).
// One warp per NODES_PER_WARP nodes. Lane l owns j in {l, l+32, l+64, l+96};
// its 4x16 W slice lives in 64 registers (loaded once). Per node:
//   - one coalesced LDG.128 wavefront for x[n][16] (lane reads chunk l&3)
//   - 16 SHFL broadcasts to distribute x scalars
//   - 64 FFMA/lane
//   - 4 coalesced STG.32 (lanes write consecutive floats per c)
// No shared memory at all => no bank conflicts.
// ---------------------------------------------------------------------------
__global__ void precompute_y_kernel(const float* __restrict__ x,
                                    const float* __restrict__ W,
                                    int N) {
    int lane = threadIdx.x & 31;
    int warp = (blockIdx.x * blockDim.x + threadIdx.x) >> 5;

    // Load this lane's W rows: j = lane + 32c, row = W + j*16 floats.
    float4 Wr[4][4];
#pragma unroll
    for (int c = 0; c < 4; ++c) {
        const float4* row = (const float4*)(W + (lane + 32 * c) * 16);
#pragma unroll
        for (int q = 0; q < 4; ++q) Wr[c][q] = row[q];
    }

    int n0 = warp * NODES_PER_WARP;
    for (int t = 0; t < NODES_PER_WARP; ++t) {
        int n = n0 + t;
        if (n >= N) return;  // warp-uniform exit

        float4 xq = ((const float4*)x)[n * 4 + (lane & 3)];

        float xs[16];
#pragma unroll
        for (int i = 0; i < 16; ++i) {
            float comp = ((i & 3) == 0) ? xq.x :
                         ((i & 3) == 1) ? xq.y :
                         ((i & 3) == 2) ? xq.z : xq.w;
            xs[i] = __shfl_sync(0xffffffffu, comp, i >> 2);
        }

        float acc[4];
#pragma unroll
        for (int c = 0; c < 4; ++c) {
            float a = 0.f;
#pragma unroll
            for (int q = 0; q < 4; ++q) {
                a += Wr[c][q].x * xs[4 * q + 0];
                a += Wr[c][q].y * xs[4 * q + 1];
                a += Wr[c][q].z * xs[4 * q + 2];
                a += Wr[c][q].w * xs[4 * q + 3];
            }
            acc[c] = a;
        }

        float* yp = g_y + (long long)n * 128 + lane;
#pragma unroll
        for (int c = 0; c < 4; ++c) yp[32 * c] = acc[c];
    }
}

// ---------------------------------------------------------------------------
// Phase 2: 8 lanes per edge. y viewed as float4[32] per node; lane s loads
// chunks {s, s+8, s+16, s+24} so each 128B line is exactly one L1tex
// wavefront (4 wavefronts/edge = minimum for a 512B gather).
// chunk j = a*4 + oc: a = 2k + (s>>2), oc = s&3. shfl_xor(4) folds the
// a-halves; lanes s<4 issue one red.global.add.v4.f32 each.
// ---------------------------------------------------------------------------
__global__ void edge_scatter_kernel(const float* __restrict__ eattr,
                                    float* __restrict__ out,
                                    long long E) {
    int lane = threadIdx.x & 31;
    long long warp_global = ((long long)blockIdx.x * blockDim.x + threadIdx.x) >> 5;
    int g = lane >> 3;   // edge slot within warp
    int s = lane & 7;    // sublane within edge

    long long e = warp_global * 4 + g;
    if (e >= E) return;

    int src = g_src[e];

    const float4* y4 = (const float4*)g_y + (long long)src * 32;
    const float* ea = eattr + e * 8;
    int ab = s >> 2;
    int oc = s & 3;

    float4 acc = make_float4(0.f, 0.f, 0.f, 0.f);
#pragma unroll
    for (int k = 0; k < 4; ++k) {
        float4 v = y4[k * 8 + s];      // 8 lanes -> one 128B line
        float w = ea[2 * k + ab];      // a = 2k + ab
        acc.x += w * v.x;
        acc.y += w * v.y;
        acc.z += w * v.z;
        acc.w += w * v.w;
    }

    unsigned mask = __activemask();
    acc.x += __shfl_xor_sync(mask, acc.x, 4);
    acc.y += __shfl_xor_sync(mask, acc.y, 4);
    acc.z += __shfl_xor_sync(mask, acc.z, 4);
    acc.w += __shfl_xor_sync(mask, acc.w, 4);

    if (ab == 0) {
        int dst = g_dst[e];
        float* p = out + (long long)dst * 16 + oc * 4;
        asm volatile("red.global.add.v4.f32 [%0], {%1, %2, %3, %4};"
                     :: "l"(p), "f"(acc.x), "f"(acc.y), "f"(acc.z), "f"(acc.w)
                     : "memory");
    }
}

// ---------------------------------------------------------------------------
// Phase 3: out = relu(out + bias)
// ---------------------------------------------------------------------------
__global__ void bias_relu_kernel(float* __restrict__ out,
                                 const float* __restrict__ bias,
                                 int total4) {
    int i = blockIdx.x * blockDim.x + threadIdx.x;
    if (i >= total4) return;
    float4 v = ((float4*)out)[i];
    float4 b = ((const float4*)bias)[i & 3];
    v.x = fmaxf(v.x + b.x, 0.f);
    v.y = fmaxf(v.y + b.y, 0.f);
    v.z = fmaxf(v.z + b.z, 0.f);
    v.w = fmaxf(v.w + b.w, 0.f);
    ((float4*)out)[i] = v;
}

// ---------------------------------------------------------------------------
// inputs (metadata order): x[N,16] f32, edge_index[2,E] (i32 or i64),
//   edge_attr[E,8] f32, weight_matrix[8,16,16] f32, bias[16] f32, num_nodes
// output: [N,16] f32
// ---------------------------------------------------------------------------
extern "C" void kernel_launch(void* const* d_in, const int* in_sizes, int n_in,
                              void* d_out, int out_size) {
    const float* x = (const float*)d_in[0];
    const void* ei = d_in[1];
    const float* eattr = (const float*)d_in[2];
    const float* W = (const float*)d_in[3];
    const float* bias = (const float*)d_in[4];

    int N = in_sizes[0] / 16;
    long long E = (long long)in_sizes[2] / 8;
    float* out = (float*)d_out;

    // dtype detect + edge conversion
    {
        int n_pairs = (int)((E < 2048) ? E : 2048);
        detect_dtype_kernel<<<1, 256>>>((const int*)ei, n_pairs);
        int blocks = (int)((E + 255) / 256);
        convert_edges_kernel<<<blocks, 256>>>(ei, E);
    }
    // Phase 0: zero output
    {
        int n4 = out_size / 4;
        zero_out_kernel<<<(n4 + 255) / 256, 256>>>((float4*)out, n4);
    }
    // Phase 1: per-node precompute (warp per NODES_PER_WARP nodes)
    {
        long long warps = ((long long)N + NODES_PER_WARP - 1) / NODES_PER_WARP;
        long long threads = warps * 32;
        int blocks = (int)((threads + 255) / 256);
        precompute_y_kernel<<<blocks, 256>>>(x, W, N);
    }
    // Phase 2: edge gather/scatter
    {
        long long warps = (E + 3) / 4;
        long long threads = warps * 32;
        int blocks = (int)((threads + 255) / 256);
        edge_scatter_kernel<<<blocks, 256>>>(eattr, out, E);
    }
    // Phase 3: bias + relu
    {
        int total4 = out_size / 4;
        bias_relu_kernel<<<(total4 + 255) / 256, 256>>>(out, bias, total4);
    }
}